// round 2
// baseline (speedup 1.0000x reference)
#include <cuda_runtime.h>

typedef unsigned long long u64;

#define H 1024
#define W 1024
#define PLANES 24
#define TH 16
#define TW 128
#define BX 16
#define BY 16
#define SROWS (TH + 3)       // 19
#define SCOLS (TW + 8)       // 136
#define NBX (W / TW)         // 8
#define NBY (H / TH)         // 64
#define NT (NBX * NBY * PLANES)  // 12288 tiles
#define TPB 8                // tiles per block (contiguous in x)
#define NBLK (NT / TPB)      // 1536 blocks

__device__ float g_partials[NBLK];

__device__ __forceinline__ u64 add2(u64 a, u64 b) {
    u64 r;
    asm("add.rn.f32x2 %0, %1, %2;" : "=l"(r) : "l"(a), "l"(b));
    return r;
}
__device__ __forceinline__ u64 pk(float lo, float hi) {
    u64 r;
    asm("mov.b64 %0, {%1, %2};" : "=l"(r)
        : "r"(__float_as_uint(lo)), "r"(__float_as_uint(hi)));
    return r;
}
__device__ __forceinline__ float2 unpk(u64 v) {
    unsigned lo, hi;
    asm("mov.b64 {%0, %1}, %2;" : "=r"(lo), "=r"(hi) : "l"(v));
    return make_float2(__uint_as_float(lo), __uint_as_float(hi));
}

#define ABSM 0x7FFFFFFF7FFFFFFFULL

__global__ __launch_bounds__(BX * BY) void btv_kernel(const float* __restrict__ x) {
    __shared__ __align__(16) float s[SROWS][SCOLS];
    __shared__ float warp_sums[(BX * BY) / 32];

    const int tx = threadIdx.x;
    const int ty = threadIdx.y;
    const int tid = ty * BX + tx;

    u64 acc0 = 0ull, acc1 = 0ull, acc2r = 0ull, acc3 = 0ull;

    const int t0 = blockIdx.x * TPB;
#pragma unroll 1
    for (int ti = 0; ti < TPB; ++ti) {
        const int t = t0 + ti;
        const int px = t & (NBX - 1);
        const int py = (t >> 3) & (NBY - 1);
        const int pz = t >> 9;
        const int tile_x = px * TW;
        const int tile_y = py * TH;
        const float* plane = x + (size_t)pz * (H * W);

        if (ti) __syncthreads();  // protect smem reuse
        for (int idx = tid; idx < SROWS * SCOLS; idx += BX * BY) {
            int r = idx / SCOLS;
            int c = idx - r * SCOLS;
            int gr = (tile_y + r) & (H - 1);
            int gc = (tile_x + c - 4) & (W - 1);
            s[r][c] = plane[gr * W + gc];
        }
        __syncthreads();

        u64 acc[4] = {0ull, 0ull, 0ull, 0ull};
        u64 nc[4];

        // k = 0 row: provides centers (w[4..11]) and dl = 1,2,3 terms
        {
            const float* rowp = &s[ty][tx * 8];
            float w[16];
#pragma unroll
            for (int qq = 0; qq < 4; ++qq) {
                int q = (qq + (tx >> 2)) & 3;  // staggered: conflict-free LDS.128
                float4 v = *reinterpret_cast<const float4*>(rowp + 4 * q);
                w[4 * q + 0] = v.x; w[4 * q + 1] = v.y;
                w[4 * q + 2] = v.z; w[4 * q + 3] = v.w;
            }
#pragma unroll
            for (int p = 0; p < 4; ++p) {
                nc[p] = pk(__uint_as_float(__float_as_uint(w[4 + 2 * p]) ^ 0x80000000u),
                           __uint_as_float(__float_as_uint(w[5 + 2 * p]) ^ 0x80000000u));
            }
#pragma unroll
            for (int p = 0; p < 4; ++p) {
                u64 d;
                d = add2(pk(w[2 * p + 5], w[2 * p + 6]), nc[p]) & ABSM;  // dl=1
                acc[p] = add2(acc[p], d);
                d = add2(pk(w[2 * p + 6], w[2 * p + 7]), nc[p]) & ABSM;  // dl=2
                acc[p] = add2(acc[p], d);
                d = add2(pk(w[2 * p + 7], w[2 * p + 8]), nc[p]) & ABSM;  // dl=3
                acc[p] = add2(acc[p], d);
            }
        }

        // k = 1..3 rows: dl = -3..3 (7 offsets each)
#pragma unroll
        for (int k = 1; k <= 3; ++k) {
            const float* rowp = &s[ty + k][tx * 8];
            float w[16];
#pragma unroll
            for (int qq = 0; qq < 4; ++qq) {
                int q = (qq + (tx >> 2)) & 3;
                float4 v = *reinterpret_cast<const float4*>(rowp + 4 * q);
                w[4 * q + 0] = v.x; w[4 * q + 1] = v.y;
                w[4 * q + 2] = v.z; w[4 * q + 3] = v.w;
            }
#pragma unroll
            for (int p = 0; p < 4; ++p) {
                u64 d;
                d = add2(pk(w[2 * p + 1], w[2 * p + 2]), nc[p]) & ABSM;  // dl=-3
                acc[p] = add2(acc[p], d);
                d = add2(pk(w[2 * p + 2], w[2 * p + 3]), nc[p]) & ABSM;  // dl=-2
                acc[p] = add2(acc[p], d);
                d = add2(pk(w[2 * p + 3], w[2 * p + 4]), nc[p]) & ABSM;  // dl=-1
                acc[p] = add2(acc[p], d);
                d = add2(pk(w[2 * p + 4], w[2 * p + 5]), nc[p]) & ABSM;  // dl=0
                acc[p] = add2(acc[p], d);
                d = add2(pk(w[2 * p + 5], w[2 * p + 6]), nc[p]) & ABSM;  // dl=1
                acc[p] = add2(acc[p], d);
                d = add2(pk(w[2 * p + 6], w[2 * p + 7]), nc[p]) & ABSM;  // dl=2
                acc[p] = add2(acc[p], d);
                d = add2(pk(w[2 * p + 7], w[2 * p + 8]), nc[p]) & ABSM;  // dl=3
                acc[p] = add2(acc[p], d);
            }
        }

        acc0 = add2(acc0, acc[0]);
        acc1 = add2(acc1, acc[1]);
        acc2r = add2(acc2r, acc[2]);
        acc3 = add2(acc3, acc[3]);
    }

    float2 a0 = unpk(acc0), a1 = unpk(acc1), a2 = unpk(acc2r), a3 = unpk(acc3);
    float accf = ((a0.x + a0.y) + (a1.x + a1.y)) + ((a2.x + a2.y) + (a3.x + a3.y));

#pragma unroll
    for (int o = 16; o > 0; o >>= 1) accf += __shfl_down_sync(0xFFFFFFFFu, accf, o);

    const int lane = tid & 31;
    const int wid = tid >> 5;
    if (lane == 0) warp_sums[wid] = accf;
    __syncthreads();

    if (tid == 0) {
        float bsum = 0.0f;
#pragma unroll
        for (int i = 0; i < (BX * BY) / 32; i++) bsum += warp_sums[i];
        g_partials[blockIdx.x] = bsum;
    }
}

__global__ void btv_reduce_kernel(float* __restrict__ out) {
    __shared__ double sm[8];
    const int tid = threadIdx.x;  // 256 threads
    double t = 0.0;
    for (int i = tid; i < NBLK; i += 256) t += (double)g_partials[i];
#pragma unroll
    for (int o = 16; o > 0; o >>= 1) t += __shfl_down_sync(0xFFFFFFFFu, t, o);
    if ((tid & 31) == 0) sm[tid >> 5] = t;
    __syncthreads();
    if (tid == 0) {
        double r = 0.0;
#pragma unroll
        for (int i = 0; i < 8; i++) r += sm[i];
        // factor 2 from (k,l) <-> (-k,-l) symmetry; WEIGHT=0.1; N = 24*1024*1024
        out[0] = (float)(r * (0.2 / 25165824.0));
    }
}

extern "C" void kernel_launch(void* const* d_in, const int* in_sizes, int n_in,
                              void* d_out, int out_size) {
    (void)in_sizes; (void)n_in; (void)out_size;
    const float* x = (const float*)d_in[0];
    float* out = (float*)d_out;

    btv_kernel<<<NBLK, dim3(BX, BY)>>>(x);
    btv_reduce_kernel<<<1, 256>>>(out);
}

// round 3
// speedup vs baseline: 1.3194x; 1.3194x over previous
#include <cuda_runtime.h>

#define H 1024
#define W 1024
#define PLANES 24            // 8 * 3
#define TH 16                // tile rows per block
#define TW 128               // tile cols per block
#define RE 8                 // elements per thread (columns)
#define BX 16
#define BY 16
#define SROWS (TH + 3)       // 19
#define SCOLS (TW + 8)       // 136
#define NBX (W / TW)         // 8
#define NBY (H / TH)         // 64
#define NBLOCKS (NBX * NBY * PLANES)  // 12288

__device__ float g_partials[NBLOCKS];
__device__ int g_ctr = 0;

__global__ __launch_bounds__(BX * BY) void btv_kernel(const float* __restrict__ x,
                                                      float* __restrict__ out) {
    __shared__ __align__(16) float s[SROWS][SCOLS];
    __shared__ float warp_sums[(BX * BY) / 32];
    __shared__ int s_last;

    const int tx = threadIdx.x;
    const int ty = threadIdx.y;
    const int tid = ty * BX + tx;

    const int tile_x = blockIdx.x * TW;
    const int tile_y = blockIdx.y * TH;
    const float* plane = x + (size_t)blockIdx.z * (H * W);

    // Cooperative load of (TH+3) x (TW+8) tile with circular wrap.
    for (int idx = tid; idx < SROWS * SCOLS; idx += BX * BY) {
        int r = idx / SCOLS;
        int c = idx - r * SCOLS;
        int gr = (tile_y + r) & (H - 1);
        int gc = (tile_x + c - 4) & (W - 1);
        s[r][c] = plane[gr * W + gc];
    }
    __syncthreads();

    float ch[RE];        // 0.5 * center
    float acc[RE];
#pragma unroll
    for (int e = 0; e < RE; e++) acc[e] = 0.0f;

    // k = 0 row: centers + dl = 1..3 (symmetry covers negatives)
    {
        float w[16];
        const float* rowp = &s[ty][tx * RE];
#pragma unroll
        for (int qq = 0; qq < 4; ++qq) {
            int q = (qq + (tx >> 2)) & 3;  // staggered: conflict-free LDS.128
            float4 v = *reinterpret_cast<const float4*>(rowp + 4 * q);
            w[4 * q + 0] = v.x; w[4 * q + 1] = v.y;
            w[4 * q + 2] = v.z; w[4 * q + 3] = v.w;
        }
#pragma unroll
        for (int e = 0; e < RE; e++) ch[e] = 0.5f * w[4 + e];
#pragma unroll
        for (int dl = 1; dl <= 3; dl++) {
#pragma unroll
            for (int e = 0; e < RE; e++) {
                float d = __fmaf_rn(w[4 + e + dl], -0.5f, ch[e]);   // FFMA-imm
                acc[e] = __fmaf_rn(fabsf(d), 0.5f, acc[e]);         // FFMA-imm
            }
        }
    }

    // k = 1..3 rows: dl = -3..3
#pragma unroll
    for (int k = 1; k <= 3; ++k) {
        float w[16];
        const float* rowp = &s[ty + k][tx * RE];
#pragma unroll
        for (int qq = 0; qq < 4; ++qq) {
            int q = (qq + (tx >> 2)) & 3;
            float4 v = *reinterpret_cast<const float4*>(rowp + 4 * q);
            w[4 * q + 0] = v.x; w[4 * q + 1] = v.y;
            w[4 * q + 2] = v.z; w[4 * q + 3] = v.w;
        }
#pragma unroll
        for (int dl = -3; dl <= 3; dl++) {
#pragma unroll
            for (int e = 0; e < RE; e++) {
                float d = __fmaf_rn(w[4 + e + dl], -0.5f, ch[e]);
                acc[e] = __fmaf_rn(fabsf(d), 0.5f, acc[e]);
            }
        }
    }

    float accf = ((acc[0] + acc[1]) + (acc[2] + acc[3])) +
                 ((acc[4] + acc[5]) + (acc[6] + acc[7]));

#pragma unroll
    for (int o = 16; o > 0; o >>= 1) accf += __shfl_down_sync(0xFFFFFFFFu, accf, o);

    const int lane = tid & 31;
    const int wid = tid >> 5;
    if (lane == 0) warp_sums[wid] = accf;
    __syncthreads();

    if (tid == 0) {
        float bsum = 0.0f;
#pragma unroll
        for (int i = 0; i < (BX * BY) / 32; i++) bsum += warp_sums[i];
        int bidx = (blockIdx.z * gridDim.y + blockIdx.y) * gridDim.x + blockIdx.x;
        g_partials[bidx] = bsum;
        __threadfence();
        int done = atomicAdd(&g_ctr, 1);
        s_last = (done == NBLOCKS - 1) ? 1 : 0;
    }
    __syncthreads();

    // Last block to finish reduces all partials (fixed order -> deterministic).
    if (s_last) {
        double t = 0.0;
        for (int i = tid; i < NBLOCKS; i += BX * BY) t += (double)g_partials[i];
#pragma unroll
        for (int o = 16; o > 0; o >>= 1) t += __shfl_down_sync(0xFFFFFFFFu, t, o);
        __shared__ double sm[(BX * BY) / 32];
        if (lane == 0) sm[wid] = t;
        __syncthreads();
        if (tid == 0) {
            double r = 0.0;
#pragma unroll
            for (int i = 0; i < (BX * BY) / 32; i++) r += sm[i];
            // acc holds sum/4; symmetry factor 2; WEIGHT=0.1; N = 24*1024*1024
            out[0] = (float)(r * (0.8 / 25165824.0));
            atomicExch(&g_ctr, 0);  // reset for next graph replay
        }
    }
}

extern "C" void kernel_launch(void* const* d_in, const int* in_sizes, int n_in,
                              void* d_out, int out_size) {
    (void)in_sizes; (void)n_in; (void)out_size;
    const float* x = (const float*)d_in[0];
    float* out = (float*)d_out;

    dim3 grid(NBX, NBY, PLANES);
    dim3 block(BX, BY);
    btv_kernel<<<grid, block>>>(x, out);
}

// round 4
// speedup vs baseline: 3.6555x; 2.7707x over previous
#include <cuda_runtime.h>
#include <cuda_fp16.h>

#define H 1024
#define W 1024
#define PLANES 24              // 8 * 3
#define THRAW 32               // raw output rows per tile
#define PACK 16                // row-pack stride (.x = r, .y = r+16)
#define TW 128                 // tile cols
#define RE 8                   // cols per thread
#define BX 16
#define BY 16                  // packed rows per tile
#define PROWS (BY + 3)         // 19 packed rows (k halo)
#define SCOLS (TW + 8)         // 136 (col halo: -4..+3 extra)
#define NBX (W / TW)           // 8
#define NBY (H / THRAW)        // 32
#define NBLOCKS (NBX * NBY * PLANES)  // 6144

__device__ float g_partials[NBLOCKS];
__device__ int g_ctr = 0;

__global__ __launch_bounds__(BX * BY) void btv_kernel(const float* __restrict__ x,
                                                      float* __restrict__ out) {
    __shared__ __align__(16) __half2 s[PROWS][SCOLS];
    __shared__ float warp_sums[(BX * BY) / 32];
    __shared__ int s_last;

    const int tx = threadIdx.x;
    const int ty = threadIdx.y;
    const int tid = ty * BX + tx;

    const int tile_x = blockIdx.x * TW;
    const int tile_y = blockIdx.y * THRAW;
    const float* plane = x + (size_t)blockIdx.z * (H * W);

    // Cooperative load: packed row pr holds raw rows (tile_y+pr, tile_y+pr+16),
    // shared col c maps to raw col (tile_x + c - 4) & (W-1). fp32 -> fp16x2.
    for (int idx = tid; idx < PROWS * SCOLS; idx += BX * BY) {
        int r = idx / SCOLS;
        int c = idx - r * SCOLS;
        int gr0 = (tile_y + r) & (H - 1);
        int gr1 = (tile_y + r + PACK) & (H - 1);
        int gc = (tile_x + c - 4) & (W - 1);
        float v0 = plane[gr0 * W + gc];
        float v1 = plane[gr1 * W + gc];
        s[r][c] = __floats2half2_rn(v0, v1);
    }
    __syncthreads();

    __half2 c2[RE];
    __half2 acc[RE];
#pragma unroll
    for (int e = 0; e < RE; e++) acc[e] = __floats2half2_rn(0.0f, 0.0f);

    // Window: w[i] = s[row][tx*8 + i]; center e -> w[4+e]; neighbor dl -> w[4+e+dl].
    // k = 0 row: centers + dl = 1..3 (symmetry (k,l)<->(-k,-l) covers the rest)
    {
        __half2 w[16];
        const float4* rowp = reinterpret_cast<const float4*>(&s[ty][tx * RE]);
#pragma unroll
        for (int q = 0; q < 4; ++q) {
            float4 v = rowp[q];
            w[4 * q + 0] = *(__half2*)&v.x; w[4 * q + 1] = *(__half2*)&v.y;
            w[4 * q + 2] = *(__half2*)&v.z; w[4 * q + 3] = *(__half2*)&v.w;
        }
#pragma unroll
        for (int e = 0; e < RE; e++) c2[e] = w[4 + e];
#pragma unroll
        for (int dl = 1; dl <= 3; dl++) {
#pragma unroll
            for (int e = 0; e < RE; e++) {
                __half2 d = __habs2(__hsub2(c2[e], w[4 + e + dl]));
                acc[e] = __hadd2(acc[e], d);
            }
        }
    }

    // k = 1..3 rows: dl = -3..3
#pragma unroll
    for (int k = 1; k <= 3; ++k) {
        __half2 w[16];
        const float4* rowp = reinterpret_cast<const float4*>(&s[ty + k][tx * RE]);
#pragma unroll
        for (int q = 0; q < 4; ++q) {
            float4 v = rowp[q];
            w[4 * q + 0] = *(__half2*)&v.x; w[4 * q + 1] = *(__half2*)&v.y;
            w[4 * q + 2] = *(__half2*)&v.z; w[4 * q + 3] = *(__half2*)&v.w;
        }
#pragma unroll
        for (int dl = -3; dl <= 3; dl++) {
#pragma unroll
            for (int e = 0; e < RE; e++) {
                __half2 d = __habs2(__hsub2(c2[e], w[4 + e + dl]));
                acc[e] = __hadd2(acc[e], d);
            }
        }
    }

    // Widen to fp32 and reduce
    float accf = 0.0f;
#pragma unroll
    for (int e = 0; e < RE; e++) {
        float2 f = __half22float2(acc[e]);
        accf += f.x + f.y;
    }

#pragma unroll
    for (int o = 16; o > 0; o >>= 1) accf += __shfl_down_sync(0xFFFFFFFFu, accf, o);

    const int lane = tid & 31;
    const int wid = tid >> 5;
    if (lane == 0) warp_sums[wid] = accf;
    __syncthreads();

    if (tid == 0) {
        float bsum = 0.0f;
#pragma unroll
        for (int i = 0; i < (BX * BY) / 32; i++) bsum += warp_sums[i];
        int bidx = (blockIdx.z * gridDim.y + blockIdx.y) * gridDim.x + blockIdx.x;
        g_partials[bidx] = bsum;
        __threadfence();
        int done = atomicAdd(&g_ctr, 1);
        s_last = (done == NBLOCKS - 1) ? 1 : 0;
    }
    __syncthreads();

    // Last block reduces all partials (fixed order -> deterministic)
    if (s_last) {
        double t = 0.0;
        for (int i = tid; i < NBLOCKS; i += BX * BY) t += (double)g_partials[i];
#pragma unroll
        for (int o = 16; o > 0; o >>= 1) t += __shfl_down_sync(0xFFFFFFFFu, t, o);
        __shared__ double sm[(BX * BY) / 32];
        if (lane == 0) sm[wid] = t;
        __syncthreads();
        if (tid == 0) {
            double r = 0.0;
#pragma unroll
            for (int i = 0; i < (BX * BY) / 32; i++) r += sm[i];
            // symmetry factor 2; WEIGHT=0.1; N = 24*1024*1024
            out[0] = (float)(r * (0.2 / 25165824.0));
            atomicExch(&g_ctr, 0);  // reset for next graph replay
        }
    }
}

extern "C" void kernel_launch(void* const* d_in, const int* in_sizes, int n_in,
                              void* d_out, int out_size) {
    (void)in_sizes; (void)n_in; (void)out_size;
    const float* x = (const float*)d_in[0];
    float* out = (float*)d_out;

    dim3 grid(NBX, NBY, PLANES);
    dim3 block(BX, BY);
    btv_kernel<<<grid, block>>>(x, out);
}